// round 15
// baseline (speedup 1.0000x reference)
#include <cuda_runtime.h>
#include <cuda_bf16.h>

// Problem constants
#define BATCH   2
#define SEQ     2048
#define DIM     1024
#define HEADS   16
#define HDIM    64
#define ROWS    (BATCH * SEQ)          // 4096
#define ATTN_SCALE 0.125f              // 64^-0.5

// ---------------- scratch ----------------
__device__ float g_Q[BATCH * HEADS * SEQ * HDIM];   // [bh][n][d]
__device__ float g_K[BATCH * HEADS * SEQ * HDIM];
__device__ float g_V[BATCH * HEADS * SEQ * HDIM];
__device__ float g_AO[ROWS * DIM];                  // [b*SEQ+n][dim]

// ---------------- tf32 helpers ----------------
__device__ __forceinline__ float tf32r(float x) {
    unsigned u;
    asm("cvt.rna.tf32.f32 %0, %1;" : "=r"(u) : "f"(x));
    return __uint_as_float(u);
}
__device__ __forceinline__ unsigned tf32b(float x) {
    unsigned u;
    asm("cvt.rna.tf32.f32 %0, %1;" : "=r"(u) : "f"(x));
    return u;
}

__device__ __forceinline__ void mma_tf32(float c[4],
                                         unsigned a0, unsigned a1, unsigned a2, unsigned a3,
                                         unsigned b0, unsigned b1)
{
    asm("mma.sync.aligned.m16n8k8.row.col.f32.tf32.tf32.f32 "
        "{%0,%1,%2,%3}, {%4,%5,%6,%7}, {%8,%9}, {%0,%1,%2,%3};"
        : "+f"(c[0]), "+f"(c[1]), "+f"(c[2]), "+f"(c[3])
        : "r"(a0), "r"(a1), "r"(a2), "r"(a3), "r"(b0), "r"(b1));
}

// ---------------- cp.async helpers ----------------
__device__ __forceinline__ void cp_async16(void* smem_ptr, const void* gmem_ptr) {
    unsigned saddr = (unsigned)__cvta_generic_to_shared(smem_ptr);
    asm volatile("cp.async.ca.shared.global [%0], [%1], 16;"
                 :: "r"(saddr), "l"(gmem_ptr));
}
#define CP_COMMIT() asm volatile("cp.async.commit_group;" ::: "memory")
#define CP_WAIT1()  asm volatile("cp.async.wait_group 1;" ::: "memory")
#define CP_WAIT2()  asm volatile("cp.async.wait_group 2;" ::: "memory")

struct GemmPtrs {
    const float* A[3];
    const float* B[3];
    float*       C[3];
};

// ---------------- tf32 tensor-core GEMM ----------------
// Block tile 128x128, BK=32. 128 threads, 4 warps of 64x64 each.
// 3-stage cp.async pipeline (prefetch distance 3 tiles hides L2 latency behind
// two mma blocks). Raw fp32 in smem, cvt.rna at fragment load.
#define AS_STAGE (128 * 36)
#define BS_STAGE (32 * 132)
#define GEMM_SMEM ((3 * AS_STAGE + 3 * BS_STAGE) * (int)sizeof(float))   // 105984 B

template <int SPLIT_HEADS>
__global__ void __launch_bounds__(128, 2)
gemm_tc(GemmPtrs p, const float* __restrict__ bias)
{
    extern __shared__ float smem_g[];
    float* As = smem_g;                  // [3][128][36]
    float* Bs = smem_g + 3 * AS_STAGE;   // [3][32][132]

    const float* __restrict__ A = p.A[blockIdx.z];
    const float* __restrict__ B = p.B[blockIdx.z];
    float* __restrict__ C       = p.C[blockIdx.z];

    const int tid  = threadIdx.x;
    const int warp = tid >> 5;        // 0..3
    const int lane = tid & 31;
    const int r    = lane >> 2;       // 0..7
    const int c    = lane & 3;        // 0..3
    const int wm   = (warp & 1) * 64;
    const int wn   = (warp >> 1) * 64;
    const int row0 = blockIdx.y * 128;
    const int col0 = blockIdx.x * 128;

    // loader coordinates: 8 A-chunks + 8 B-chunks per thread per stage.
    const int a_m0 = tid >> 3;          // 0..15
    const int a_k4 = (tid & 7) * 4;     // 0..28
    const int b_k0 = tid >> 5;          // 0..3
    const int b_n4 = (tid & 31) * 4;    // 0..124

    float acc[4][8][4];
#pragma unroll
    for (int i = 0; i < 4; i++)
#pragma unroll
        for (int j = 0; j < 8; j++)
#pragma unroll
            for (int t = 0; t < 4; t++) acc[i][j][t] = 0.f;

    const int NT = DIM / 32;   // 32 k-tiles

    // prologue: async-load k-tiles 0,1,2 into stages 0,1,2
#pragma unroll
    for (int s = 0; s < 3; s++) {
#pragma unroll
        for (int j = 0; j < 8; j++) {
            cp_async16(&As[s * AS_STAGE + (a_m0 + j * 16) * 36 + a_k4],
                       &A[(size_t)(row0 + a_m0 + j * 16) * DIM + s * 32 + a_k4]);
            cp_async16(&Bs[s * BS_STAGE + (b_k0 + j * 4) * 132 + b_n4],
                       &B[(size_t)(s * 32 + b_k0 + j * 4) * DIM + col0 + b_n4]);
        }
        CP_COMMIT();
    }

    int st = 0;
    for (int kt = 0; kt < NT; kt++) {
        CP_WAIT2();            // tile kt's group complete (3 in flight max)
        __syncthreads();

        const float* Asb = &As[st * AS_STAGE];
        const float* Bsb = &Bs[st * BS_STAGE];

#pragma unroll
        for (int ks = 0; ks < 4; ks++) {
            const int kb = ks * 8;
            unsigned a[4][4];
#pragma unroll
            for (int i = 0; i < 4; i++) {
                a[i][0] = tf32b(Asb[(wm + i * 16 + r    ) * 36 + kb + c    ]);
                a[i][1] = tf32b(Asb[(wm + i * 16 + r + 8) * 36 + kb + c    ]);
                a[i][2] = tf32b(Asb[(wm + i * 16 + r    ) * 36 + kb + c + 4]);
                a[i][3] = tf32b(Asb[(wm + i * 16 + r + 8) * 36 + kb + c + 4]);
            }
#pragma unroll
            for (int j = 0; j < 8; j++) {
                unsigned b0 = tf32b(Bsb[(kb + c    ) * 132 + wn + j * 8 + r]);
                unsigned b1 = tf32b(Bsb[(kb + c + 4) * 132 + wn + j * 8 + r]);
#pragma unroll
                for (int i = 0; i < 4; i++)
                    mma_tf32(acc[i][j], a[i][0], a[i][1], a[i][2], a[i][3], b0, b1);
            }
        }
        __syncthreads();       // all warps done with stage st before refill

        if (kt + 3 < NT) {
            const int k0 = (kt + 3) * 32;
#pragma unroll
            for (int j = 0; j < 8; j++) {
                cp_async16(&As[st * AS_STAGE + (a_m0 + j * 16) * 36 + a_k4],
                           &A[(size_t)(row0 + a_m0 + j * 16) * DIM + k0 + a_k4]);
                cp_async16(&Bs[st * BS_STAGE + (b_k0 + j * 4) * 132 + b_n4],
                           &B[(size_t)(k0 + b_k0 + j * 4) * DIM + col0 + b_n4]);
            }
        }
        CP_COMMIT();           // one group per iter (possibly empty near tail)
        st = (st == 2) ? 0 : st + 1;
    }

    // epilogue
#pragma unroll
    for (int i = 0; i < 4; i++) {
#pragma unroll
        for (int j = 0; j < 8; j++) {
            const int mlo = row0 + wm + i * 16 + r;
            const int mhi = mlo + 8;
            const int col = col0 + wn + j * 8 + c * 2;
            if (SPLIT_HEADS) {
                const int h = col >> 6, d = col & 63;
                {
                    const int b = mlo >> 11, n = mlo & (SEQ - 1);
                    float* dst = &C[(((size_t)(b * HEADS + h) * SEQ + n) * HDIM) + d];
                    *(float2*)dst = make_float2(acc[i][j][0], acc[i][j][1]);
                }
                {
                    const int b = mhi >> 11, n = mhi & (SEQ - 1);
                    float* dst = &C[(((size_t)(b * HEADS + h) * SEQ + n) * HDIM) + d];
                    *(float2*)dst = make_float2(acc[i][j][2], acc[i][j][3]);
                }
            } else {
                const float b0 = bias[col], b1 = bias[col + 1];
                *(float2*)&C[(size_t)mlo * DIM + col] =
                    make_float2(acc[i][j][0] + b0, acc[i][j][1] + b1);
                *(float2*)&C[(size_t)mhi * DIM + col] =
                    make_float2(acc[i][j][2] + b0, acc[i][j][3] + b1);
            }
        }
    }
}

// ---------------- tf32 tensor-core flash attention (round-12, unchanged) ----------------
// grid: (SEQ/128, BATCH*HEADS), 128 threads (4 warps); warp owns 32 q-rows.
// K/V tiles: 2-stage cp.async double buffer. Q fragments in registers throughout.
#define SLD 68                       // padded row stride (16B-aligned rows)
#define KV_STAGE (64 * SLD)
#define ATTN_SMEM ((4 * KV_STAGE + 128 * SLD) * (int)sizeof(float))   // 104448 B

__global__ void __launch_bounds__(128, 2)
attn_tc(const float* __restrict__ Q, const float* __restrict__ K,
        const float* __restrict__ V, float* __restrict__ AO)
{
    extern __shared__ float sm[];
    float* KsB = sm;                     // [2][64*SLD]
    float* VsB = sm + 2 * KV_STAGE;      // [2][64*SLD]
    float* Ps  = sm + 4 * KV_STAGE;      // [128*SLD]

    const int tid  = threadIdx.x;
    const int warp = tid >> 5;
    const int lane = tid & 31;
    const int r    = lane >> 2;     // 0..7
    const int c    = lane & 3;      // 0..3
    const int wr   = warp * 32;     // warp's q-row base within 128-row tile
    const int bh   = blockIdx.y;
    const int q0   = blockIdx.x * 128;

    const float* Qg = Q + ((size_t)bh * SEQ + q0) * HDIM;
    const float* Kg = K + (size_t)bh * SEQ * HDIM;
    const float* Vg = V + (size_t)bh * SEQ * HDIM;

    const int l_r0 = tid >> 4;          // 0..7
    const int l_c4 = (tid & 15) * 4;    // 0..60

    // Q fragments (scale folded in): 2 m-tiles x 8 ksteps x 4 regs
    unsigned qf[2][8][4];
#pragma unroll
    for (int i = 0; i < 2; i++) {
        const int rb = wr + i * 16;
#pragma unroll
        for (int ks = 0; ks < 8; ks++) {
            const int kb = ks * 8;
            qf[i][ks][0] = tf32b(Qg[(rb + r    ) * HDIM + kb + c    ] * ATTN_SCALE);
            qf[i][ks][1] = tf32b(Qg[(rb + r + 8) * HDIM + kb + c    ] * ATTN_SCALE);
            qf[i][ks][2] = tf32b(Qg[(rb + r    ) * HDIM + kb + c + 4] * ATTN_SCALE);
            qf[i][ks][3] = tf32b(Qg[(rb + r + 8) * HDIM + kb + c + 4] * ATTN_SCALE);
        }
    }

    float mst[2][2] = {{-1e30f, -1e30f}, {-1e30f, -1e30f}};
    float lst[2][2] = {{0.f, 0.f}, {0.f, 0.f}};
    float o[2][8][4];
#pragma unroll
    for (int i = 0; i < 2; i++)
#pragma unroll
        for (int nt = 0; nt < 8; nt++)
#pragma unroll
            for (int t = 0; t < 4; t++) o[i][nt][t] = 0.f;

    const int NKT = SEQ / 64;   // 32 KV tiles

    // prologue: async-load KV tiles 0 and 1
#pragma unroll
    for (int s = 0; s < 2; s++) {
#pragma unroll
        for (int j = 0; j < 8; j++) {
            const int row = l_r0 + j * 8;
            cp_async16(&KsB[s * KV_STAGE + row * SLD + l_c4],
                       &Kg[(size_t)(s * 64 + row) * HDIM + l_c4]);
            cp_async16(&VsB[s * KV_STAGE + row * SLD + l_c4],
                       &Vg[(size_t)(s * 64 + row) * HDIM + l_c4]);
        }
        CP_COMMIT();
    }

    for (int t = 0; t < NKT; t++) {
        const int st = t & 1;
        CP_WAIT1();
        __syncthreads();

        const float* Ks = &KsB[st * KV_STAGE];
        const float* Vs = &VsB[st * KV_STAGE];

        // ---- S = (Q*scale) K^T via mma ----
        float s[2][8][4];
#pragma unroll
        for (int i = 0; i < 2; i++)
#pragma unroll
            for (int nt = 0; nt < 8; nt++)
#pragma unroll
                for (int tt = 0; tt < 4; tt++) s[i][nt][tt] = 0.f;

#pragma unroll
        for (int ks = 0; ks < 8; ks++) {
            const int kb = ks * 8;
#pragma unroll
            for (int nt = 0; nt < 8; nt++) {
                unsigned b0 = tf32b(Ks[(nt * 8 + r) * SLD + kb + c    ]);
                unsigned b1 = tf32b(Ks[(nt * 8 + r) * SLD + kb + c + 4]);
                mma_tf32(s[0][nt], qf[0][ks][0], qf[0][ks][1], qf[0][ks][2], qf[0][ks][3], b0, b1);
                mma_tf32(s[1][nt], qf[1][ks][0], qf[1][ks][1], qf[1][ks][2], qf[1][ks][3], b0, b1);
            }
        }

        // ---- online softmax (warp-local quad shuffle), per m-tile ----
        float alpha[2][2];
#pragma unroll
        for (int i = 0; i < 2; i++) {
            float tl = -1e30f, th = -1e30f;
#pragma unroll
            for (int nt = 0; nt < 8; nt++) {
                tl = fmaxf(tl, fmaxf(s[i][nt][0], s[i][nt][1]));
                th = fmaxf(th, fmaxf(s[i][nt][2], s[i][nt][3]));
            }
            tl = fmaxf(tl, __shfl_xor_sync(0xffffffffu, tl, 1));
            tl = fmaxf(tl, __shfl_xor_sync(0xffffffffu, tl, 2));
            th = fmaxf(th, __shfl_xor_sync(0xffffffffu, th, 1));
            th = fmaxf(th, __shfl_xor_sync(0xffffffffu, th, 2));

            const float ml2 = fmaxf(mst[i][0], tl);
            const float mh2 = fmaxf(mst[i][1], th);
            alpha[i][0] = __expf(mst[i][0] - ml2);
            alpha[i][1] = __expf(mst[i][1] - mh2);

            float pl = 0.f, ph = 0.f;
            const int rb = wr + i * 16;
#pragma unroll
            for (int nt = 0; nt < 8; nt++) {
                float p0 = __expf(s[i][nt][0] - ml2);
                float p1 = __expf(s[i][nt][1] - ml2);
                float p2 = __expf(s[i][nt][2] - mh2);
                float p3 = __expf(s[i][nt][3] - mh2);
                pl += p0 + p1;
                ph += p2 + p3;
                *(float2*)&Ps[(rb + r    ) * SLD + nt * 8 + c * 2] =
                    make_float2(tf32r(p0), tf32r(p1));
                *(float2*)&Ps[(rb + r + 8) * SLD + nt * 8 + c * 2] =
                    make_float2(tf32r(p2), tf32r(p3));
            }
            pl += __shfl_xor_sync(0xffffffffu, pl, 1);
            pl += __shfl_xor_sync(0xffffffffu, pl, 2);
            ph += __shfl_xor_sync(0xffffffffu, ph, 1);
            ph += __shfl_xor_sync(0xffffffffu, ph, 2);

            lst[i][0] = lst[i][0] * alpha[i][0] + pl;  mst[i][0] = ml2;
            lst[i][1] = lst[i][1] * alpha[i][1] + ph;  mst[i][1] = mh2;

#pragma unroll
            for (int nt = 0; nt < 8; nt++) {
                o[i][nt][0] *= alpha[i][0]; o[i][nt][1] *= alpha[i][0];
                o[i][nt][2] *= alpha[i][1]; o[i][nt][3] *= alpha[i][1];
            }
        }
        __syncwarp();   // P strips are warp-private (rows wr..wr+31)

        // ---- O += P V via mma ----
#pragma unroll
        for (int ks = 0; ks < 8; ks++) {
            const int kb = ks * 8;
            unsigned pa[2][4];
#pragma unroll
            for (int i = 0; i < 2; i++) {
                const int rb = wr + i * 16;
                pa[i][0] = __float_as_uint(Ps[(rb + r    ) * SLD + kb + c    ]);
                pa[i][1] = __float_as_uint(Ps[(rb + r + 8) * SLD + kb + c    ]);
                pa[i][2] = __float_as_uint(Ps[(rb + r    ) * SLD + kb + c + 4]);
                pa[i][3] = __float_as_uint(Ps[(rb + r + 8) * SLD + kb + c + 4]);
            }
#pragma unroll
            for (int nt = 0; nt < 8; nt++) {
                unsigned b0 = tf32b(Vs[(kb + c    ) * SLD + nt * 8 + r]);
                unsigned b1 = tf32b(Vs[(kb + c + 4) * SLD + nt * 8 + r]);
                mma_tf32(o[0][nt], pa[0][0], pa[0][1], pa[0][2], pa[0][3], b0, b1);
                mma_tf32(o[1][nt], pa[1][0], pa[1][1], pa[1][2], pa[1][3], b0, b1);
            }
        }
        __syncthreads();   // all warps done with stage st before overwrite

        if (t + 2 < NKT) {
            const int kt2 = (t + 2) * 64;
#pragma unroll
            for (int j = 0; j < 8; j++) {
                const int row = l_r0 + j * 8;
                cp_async16(&KsB[st * KV_STAGE + row * SLD + l_c4],
                           &Kg[(size_t)(kt2 + row) * HDIM + l_c4]);
                cp_async16(&VsB[st * KV_STAGE + row * SLD + l_c4],
                           &Vg[(size_t)(kt2 + row) * HDIM + l_c4]);
            }
        }
        CP_COMMIT();
    }

    // epilogue: normalize, write [b][n][h*64+d]
    const int b = bh >> 4;
    const int h = bh & 15;
#pragma unroll
    for (int i = 0; i < 2; i++) {
        const float il = 1.0f / lst[i][0];
        const float ih = 1.0f / lst[i][1];
        const int rlo = q0 + wr + i * 16 + r;
        const int rhi = rlo + 8;
        float* dlo = &g_AO[((size_t)(b * SEQ + rlo)) * DIM + h * HDIM];
        float* dhi = &g_AO[((size_t)(b * SEQ + rhi)) * DIM + h * HDIM];
#pragma unroll
        for (int nt = 0; nt < 8; nt++) {
            const int d0 = nt * 8 + c * 2;
            *(float2*)&dlo[d0] = make_float2(o[i][nt][0] * il, o[i][nt][1] * il);
            *(float2*)&dhi[d0] = make_float2(o[i][nt][2] * ih, o[i][nt][3] * ih);
        }
    }
}

// ---------------- launch ----------------
extern "C" void kernel_launch(void* const* d_in, const int* in_sizes, int n_in,
                              void* d_out, int out_size)
{
    const float* x  = (const float*)d_in[0];
    const float* y  = (const float*)d_in[1];
    const float* Wq = (const float*)d_in[2];
    const float* Wk = (const float*)d_in[3];
    const float* Wv = (const float*)d_in[4];
    const float* Wp = (const float*)d_in[5];
    const float* bp = (const float*)d_in[6];
    float* out = (float*)d_out;

    float *qb, *kb, *vb, *ao;
    cudaGetSymbolAddress((void**)&qb, g_Q);
    cudaGetSymbolAddress((void**)&kb, g_K);
    cudaGetSymbolAddress((void**)&vb, g_V);
    cudaGetSymbolAddress((void**)&ao, g_AO);

    cudaFuncSetAttribute(gemm_tc<1>, cudaFuncAttributeMaxDynamicSharedMemorySize, GEMM_SMEM);
    cudaFuncSetAttribute(gemm_tc<0>, cudaFuncAttributeMaxDynamicSharedMemorySize, GEMM_SMEM);
    cudaFuncSetAttribute(attn_tc,    cudaFuncAttributeMaxDynamicSharedMemorySize, ATTN_SMEM);

    // QKV projections: one z-batched launch (z=0: x@Wq, z=1: y@Wk, z=2: y@Wv)
    GemmPtrs qkv;
    qkv.A[0] = x;  qkv.A[1] = y;  qkv.A[2] = y;
    qkv.B[0] = Wq; qkv.B[1] = Wk; qkv.B[2] = Wv;
    qkv.C[0] = qb; qkv.C[1] = kb; qkv.C[2] = vb;
    dim3 qkv_grid(DIM / 128, ROWS / 128, 3);   // (8, 32, 3) = 768 CTAs
    gemm_tc<1><<<qkv_grid, 128, GEMM_SMEM>>>(qkv, nullptr);

    dim3 agrid(SEQ / 128, BATCH * HEADS);      // (16, 32) = 512 CTAs
    attn_tc<<<agrid, 128, ATTN_SMEM>>>(qb, kb, vb, ao);

    // output projection
    GemmPtrs po;
    po.A[0] = ao; po.B[0] = Wp; po.C[0] = out;
    po.A[1] = po.A[2] = nullptr; po.B[1] = po.B[2] = nullptr; po.C[1] = po.C[2] = nullptr;
    dim3 ogrid(DIM / 128, ROWS / 128, 1);
    gemm_tc<0><<<ogrid, 128, GEMM_SMEM>>>(po, bp);
}

// round 16
// speedup vs baseline: 1.1148x; 1.1148x over previous
#include <cuda_runtime.h>
#include <cuda_bf16.h>

// Problem constants
#define BATCH   2
#define SEQ     2048
#define DIM     1024
#define HEADS   16
#define HDIM    64
#define ROWS    (BATCH * SEQ)          // 4096
#define ATTN_SCALE 0.125f              // 64^-0.5 (power of two: exact on tf32)

// ---------------- scratch ----------------
__device__ float g_Q[BATCH * HEADS * SEQ * HDIM];   // [bh][n][d], tf32-rounded
__device__ float g_K[BATCH * HEADS * SEQ * HDIM];   // tf32-rounded
__device__ float g_V[BATCH * HEADS * SEQ * HDIM];   // tf32-rounded
__device__ float g_AO[ROWS * DIM];                  // [b*SEQ+n][dim], tf32-rounded
__device__ float g_Xr[ROWS * DIM];                  // tf32-rounded x
__device__ float g_Yr[ROWS * DIM];                  // tf32-rounded y
__device__ float g_Wr[4 * DIM * DIM];               // tf32-rounded Wq,Wk,Wv,Wp

// ---------------- tf32 helpers ----------------
__device__ __forceinline__ float tf32r(float x) {
    unsigned u;
    asm("cvt.rna.tf32.f32 %0, %1;" : "=r"(u) : "f"(x));
    return __uint_as_float(u);
}

__device__ __forceinline__ void mma_tf32(float c[4],
                                         unsigned a0, unsigned a1, unsigned a2, unsigned a3,
                                         unsigned b0, unsigned b1)
{
    asm("mma.sync.aligned.m16n8k8.row.col.f32.tf32.tf32.f32 "
        "{%0,%1,%2,%3}, {%4,%5,%6,%7}, {%8,%9}, {%0,%1,%2,%3};"
        : "+f"(c[0]), "+f"(c[1]), "+f"(c[2]), "+f"(c[3])
        : "r"(a0), "r"(a1), "r"(a2), "r"(a3), "r"(b0), "r"(b1));
}

// ---------------- cp.async helpers ----------------
__device__ __forceinline__ void cp_async16(void* smem_ptr, const void* gmem_ptr) {
    unsigned saddr = (unsigned)__cvta_generic_to_shared(smem_ptr);
    asm volatile("cp.async.ca.shared.global [%0], [%1], 16;"
                 :: "r"(saddr), "l"(gmem_ptr));
}
#define CP_COMMIT() asm volatile("cp.async.commit_group;" ::: "memory")
#define CP_WAIT1()  asm volatile("cp.async.wait_group 1;" ::: "memory")

struct GemmPtrs {
    const float* A[3];
    const float* B[3];
    float*       C[3];
};

// ---------------- prep: tf32-round inputs once ----------------
// x,y -> g_Xr, g_Yr  (grid.y selects)
__global__ void __launch_bounds__(256)
prep_xy(const float* __restrict__ x, const float* __restrict__ y,
        float* __restrict__ xr, float* __restrict__ yr)
{
    size_t i = ((size_t)blockIdx.x * 256 + threadIdx.x) * 4;
    const float* src = blockIdx.y ? y : x;
    float* dst       = blockIdx.y ? yr : xr;
    float4 v = *(const float4*)&src[i];
    v.x = tf32r(v.x); v.y = tf32r(v.y); v.z = tf32r(v.z); v.w = tf32r(v.w);
    *(float4*)&dst[i] = v;
}

struct WPtrs { const float* W[4]; };
__global__ void __launch_bounds__(256)
prep_w(WPtrs wp, float* __restrict__ wr)
{
    size_t i = ((size_t)blockIdx.x * 256 + threadIdx.x) * 4;
    const float* src = wp.W[blockIdx.y];
    float* dst       = wr + (size_t)blockIdx.y * DIM * DIM;
    float4 v = *(const float4*)&src[i];
    v.x = tf32r(v.x); v.y = tf32r(v.y); v.z = tf32r(v.z); v.w = tf32r(v.w);
    *(float4*)&dst[i] = v;
}

// ---------------- tf32 tensor-core GEMM (round-12 2-stage, cvt-free loops) ----------------
// Block tile 128x128, BK=32. 128 threads, 4 warps of 64x64 each.
// Inputs are pre-rounded tf32 values in fp32 containers -> fragment loads are
// plain LDS (no cvt). SPLIT_HEADS epilogue rounds outputs (Q/K/V feed attention).
#define AS_STAGE (128 * 36)
#define BS_STAGE (32 * 132)
#define GEMM_SMEM ((2 * AS_STAGE + 2 * BS_STAGE) * (int)sizeof(float))   // 70656 B

template <int SPLIT_HEADS>
__global__ void __launch_bounds__(128, 2)
gemm_tc(GemmPtrs p, const float* __restrict__ bias)
{
    extern __shared__ float smem_g[];
    float* As = smem_g;                  // [2][128][36]
    float* Bs = smem_g + 2 * AS_STAGE;   // [2][32][132]

    const float* __restrict__ A = p.A[blockIdx.z];
    const float* __restrict__ B = p.B[blockIdx.z];
    float* __restrict__ C       = p.C[blockIdx.z];

    const int tid  = threadIdx.x;
    const int warp = tid >> 5;        // 0..3
    const int lane = tid & 31;
    const int r    = lane >> 2;       // 0..7
    const int c    = lane & 3;        // 0..3
    const int wm   = (warp & 1) * 64;
    const int wn   = (warp >> 1) * 64;
    const int row0 = blockIdx.y * 128;
    const int col0 = blockIdx.x * 128;

    const int a_m0 = tid >> 3;          // 0..15
    const int a_k4 = (tid & 7) * 4;     // 0..28
    const int b_k0 = tid >> 5;          // 0..3
    const int b_n4 = (tid & 31) * 4;    // 0..124

    float acc[4][8][4];
#pragma unroll
    for (int i = 0; i < 4; i++)
#pragma unroll
        for (int j = 0; j < 8; j++)
#pragma unroll
            for (int t = 0; t < 4; t++) acc[i][j][t] = 0.f;

    const int NT = DIM / 32;   // 32 k-tiles

#pragma unroll
    for (int s = 0; s < 2; s++) {
#pragma unroll
        for (int j = 0; j < 8; j++) {
            cp_async16(&As[s * AS_STAGE + (a_m0 + j * 16) * 36 + a_k4],
                       &A[(size_t)(row0 + a_m0 + j * 16) * DIM + s * 32 + a_k4]);
            cp_async16(&Bs[s * BS_STAGE + (b_k0 + j * 4) * 132 + b_n4],
                       &B[(size_t)(s * 32 + b_k0 + j * 4) * DIM + col0 + b_n4]);
        }
        CP_COMMIT();
    }

    for (int kt = 0; kt < NT; kt++) {
        const int st = kt & 1;
        CP_WAIT1();
        __syncthreads();

        const float* Asb = &As[st * AS_STAGE];
        const float* Bsb = &Bs[st * BS_STAGE];

#pragma unroll
        for (int ks = 0; ks < 4; ks++) {
            const int kb = ks * 8;
            unsigned a[4][4];
#pragma unroll
            for (int i = 0; i < 4; i++) {
                a[i][0] = __float_as_uint(Asb[(wm + i * 16 + r    ) * 36 + kb + c    ]);
                a[i][1] = __float_as_uint(Asb[(wm + i * 16 + r + 8) * 36 + kb + c    ]);
                a[i][2] = __float_as_uint(Asb[(wm + i * 16 + r    ) * 36 + kb + c + 4]);
                a[i][3] = __float_as_uint(Asb[(wm + i * 16 + r + 8) * 36 + kb + c + 4]);
            }
#pragma unroll
            for (int j = 0; j < 8; j++) {
                unsigned b0 = __float_as_uint(Bsb[(kb + c    ) * 132 + wn + j * 8 + r]);
                unsigned b1 = __float_as_uint(Bsb[(kb + c + 4) * 132 + wn + j * 8 + r]);
#pragma unroll
                for (int i = 0; i < 4; i++)
                    mma_tf32(acc[i][j], a[i][0], a[i][1], a[i][2], a[i][3], b0, b1);
            }
        }
        __syncthreads();

        if (kt + 2 < NT) {
            const int k0 = (kt + 2) * 32;
#pragma unroll
            for (int j = 0; j < 8; j++) {
                cp_async16(&As[st * AS_STAGE + (a_m0 + j * 16) * 36 + a_k4],
                           &A[(size_t)(row0 + a_m0 + j * 16) * DIM + k0 + a_k4]);
                cp_async16(&Bs[st * BS_STAGE + (b_k0 + j * 4) * 132 + b_n4],
                           &B[(size_t)(k0 + b_k0 + j * 4) * DIM + col0 + b_n4]);
            }
        }
        CP_COMMIT();
    }

    // epilogue (SPLIT_HEADS rounds to tf32: Q/K/V are consumed as mma operands)
#pragma unroll
    for (int i = 0; i < 4; i++) {
#pragma unroll
        for (int j = 0; j < 8; j++) {
            const int mlo = row0 + wm + i * 16 + r;
            const int mhi = mlo + 8;
            const int col = col0 + wn + j * 8 + c * 2;
            if (SPLIT_HEADS) {
                const int h = col >> 6, d = col & 63;
                {
                    const int b = mlo >> 11, n = mlo & (SEQ - 1);
                    float* dst = &C[(((size_t)(b * HEADS + h) * SEQ + n) * HDIM) + d];
                    *(float2*)dst = make_float2(tf32r(acc[i][j][0]), tf32r(acc[i][j][1]));
                }
                {
                    const int b = mhi >> 11, n = mhi & (SEQ - 1);
                    float* dst = &C[(((size_t)(b * HEADS + h) * SEQ + n) * HDIM) + d];
                    *(float2*)dst = make_float2(tf32r(acc[i][j][2]), tf32r(acc[i][j][3]));
                }
            } else {
                const float b0 = bias[col], b1 = bias[col + 1];
                *(float2*)&C[(size_t)mlo * DIM + col] =
                    make_float2(acc[i][j][0] + b0, acc[i][j][1] + b1);
                *(float2*)&C[(size_t)mhi * DIM + col] =
                    make_float2(acc[i][j][2] + b0, acc[i][j][3] + b1);
            }
        }
    }
}

// ---------------- tf32 tensor-core flash attention (cvt-free loops) ----------------
// grid: (SEQ/128, BATCH*HEADS), 128 threads (4 warps); warp owns 32 q-rows.
// Q/K/V arrive pre-rounded -> fragment loads are plain LDS. P is rounded at
// store (computed fresh each tile). Epilogue rounds AO for the proj GEMM.
#define SLD 68                       // padded row stride (16B-aligned rows)
#define KV_STAGE (64 * SLD)
#define ATTN_SMEM ((4 * KV_STAGE + 128 * SLD) * (int)sizeof(float))   // 104448 B

__global__ void __launch_bounds__(128, 2)
attn_tc(const float* __restrict__ Q, const float* __restrict__ K,
        const float* __restrict__ V, float* __restrict__ AO)
{
    extern __shared__ float sm[];
    float* KsB = sm;                     // [2][64*SLD]
    float* VsB = sm + 2 * KV_STAGE;      // [2][64*SLD]
    float* Ps  = sm + 4 * KV_STAGE;      // [128*SLD]

    const int tid  = threadIdx.x;
    const int warp = tid >> 5;
    const int lane = tid & 31;
    const int r    = lane >> 2;     // 0..7
    const int c    = lane & 3;      // 0..3
    const int wr   = warp * 32;     // warp's q-row base within 128-row tile
    const int bh   = blockIdx.y;
    const int q0   = blockIdx.x * 128;

    const float* Qg = Q + ((size_t)bh * SEQ + q0) * HDIM;
    const float* Kg = K + (size_t)bh * SEQ * HDIM;
    const float* Vg = V + (size_t)bh * SEQ * HDIM;

    const int l_r0 = tid >> 4;          // 0..7
    const int l_c4 = (tid & 15) * 4;    // 0..60

    // Q fragments: pre-rounded tf32 * 2^-3 is still exact tf32 -> no cvt
    unsigned qf[2][8][4];
#pragma unroll
    for (int i = 0; i < 2; i++) {
        const int rb = wr + i * 16;
#pragma unroll
        for (int ks = 0; ks < 8; ks++) {
            const int kb = ks * 8;
            qf[i][ks][0] = __float_as_uint(Qg[(rb + r    ) * HDIM + kb + c    ] * ATTN_SCALE);
            qf[i][ks][1] = __float_as_uint(Qg[(rb + r + 8) * HDIM + kb + c    ] * ATTN_SCALE);
            qf[i][ks][2] = __float_as_uint(Qg[(rb + r    ) * HDIM + kb + c + 4] * ATTN_SCALE);
            qf[i][ks][3] = __float_as_uint(Qg[(rb + r + 8) * HDIM + kb + c + 4] * ATTN_SCALE);
        }
    }

    float mst[2][2] = {{-1e30f, -1e30f}, {-1e30f, -1e30f}};
    float lst[2][2] = {{0.f, 0.f}, {0.f, 0.f}};
    float o[2][8][4];
#pragma unroll
    for (int i = 0; i < 2; i++)
#pragma unroll
        for (int nt = 0; nt < 8; nt++)
#pragma unroll
            for (int t = 0; t < 4; t++) o[i][nt][t] = 0.f;

    const int NKT = SEQ / 64;   // 32 KV tiles

#pragma unroll
    for (int s = 0; s < 2; s++) {
#pragma unroll
        for (int j = 0; j < 8; j++) {
            const int row = l_r0 + j * 8;
            cp_async16(&KsB[s * KV_STAGE + row * SLD + l_c4],
                       &Kg[(size_t)(s * 64 + row) * HDIM + l_c4]);
            cp_async16(&VsB[s * KV_STAGE + row * SLD + l_c4],
                       &Vg[(size_t)(s * 64 + row) * HDIM + l_c4]);
        }
        CP_COMMIT();
    }

    for (int t = 0; t < NKT; t++) {
        const int st = t & 1;
        CP_WAIT1();
        __syncthreads();

        const float* Ks = &KsB[st * KV_STAGE];
        const float* Vs = &VsB[st * KV_STAGE];

        // ---- S = (Q*scale) K^T via mma ----
        float s[2][8][4];
#pragma unroll
        for (int i = 0; i < 2; i++)
#pragma unroll
            for (int nt = 0; nt < 8; nt++)
#pragma unroll
                for (int tt = 0; tt < 4; tt++) s[i][nt][tt] = 0.f;

#pragma unroll
        for (int ks = 0; ks < 8; ks++) {
            const int kb = ks * 8;
#pragma unroll
            for (int nt = 0; nt < 8; nt++) {
                unsigned b0 = __float_as_uint(Ks[(nt * 8 + r) * SLD + kb + c    ]);
                unsigned b1 = __float_as_uint(Ks[(nt * 8 + r) * SLD + kb + c + 4]);
                mma_tf32(s[0][nt], qf[0][ks][0], qf[0][ks][1], qf[0][ks][2], qf[0][ks][3], b0, b1);
                mma_tf32(s[1][nt], qf[1][ks][0], qf[1][ks][1], qf[1][ks][2], qf[1][ks][3], b0, b1);
            }
        }

        // ---- online softmax (warp-local quad shuffle), per m-tile ----
        float alpha[2][2];
#pragma unroll
        for (int i = 0; i < 2; i++) {
            float tl = -1e30f, th = -1e30f;
#pragma unroll
            for (int nt = 0; nt < 8; nt++) {
                tl = fmaxf(tl, fmaxf(s[i][nt][0], s[i][nt][1]));
                th = fmaxf(th, fmaxf(s[i][nt][2], s[i][nt][3]));
            }
            tl = fmaxf(tl, __shfl_xor_sync(0xffffffffu, tl, 1));
            tl = fmaxf(tl, __shfl_xor_sync(0xffffffffu, tl, 2));
            th = fmaxf(th, __shfl_xor_sync(0xffffffffu, th, 1));
            th = fmaxf(th, __shfl_xor_sync(0xffffffffu, th, 2));

            const float ml2 = fmaxf(mst[i][0], tl);
            const float mh2 = fmaxf(mst[i][1], th);
            alpha[i][0] = __expf(mst[i][0] - ml2);
            alpha[i][1] = __expf(mst[i][1] - mh2);

            float pl = 0.f, ph = 0.f;
            const int rb = wr + i * 16;
#pragma unroll
            for (int nt = 0; nt < 8; nt++) {
                float p0 = __expf(s[i][nt][0] - ml2);
                float p1 = __expf(s[i][nt][1] - ml2);
                float p2 = __expf(s[i][nt][2] - mh2);
                float p3 = __expf(s[i][nt][3] - mh2);
                pl += p0 + p1;
                ph += p2 + p3;
                *(float2*)&Ps[(rb + r    ) * SLD + nt * 8 + c * 2] =
                    make_float2(tf32r(p0), tf32r(p1));
                *(float2*)&Ps[(rb + r + 8) * SLD + nt * 8 + c * 2] =
                    make_float2(tf32r(p2), tf32r(p3));
            }
            pl += __shfl_xor_sync(0xffffffffu, pl, 1);
            pl += __shfl_xor_sync(0xffffffffu, pl, 2);
            ph += __shfl_xor_sync(0xffffffffu, ph, 1);
            ph += __shfl_xor_sync(0xffffffffu, ph, 2);

            lst[i][0] = lst[i][0] * alpha[i][0] + pl;  mst[i][0] = ml2;
            lst[i][1] = lst[i][1] * alpha[i][1] + ph;  mst[i][1] = mh2;

#pragma unroll
            for (int nt = 0; nt < 8; nt++) {
                o[i][nt][0] *= alpha[i][0]; o[i][nt][1] *= alpha[i][0];
                o[i][nt][2] *= alpha[i][1]; o[i][nt][3] *= alpha[i][1];
            }
        }
        __syncwarp();   // P strips are warp-private (rows wr..wr+31)

        // ---- O += P V via mma ----
#pragma unroll
        for (int ks = 0; ks < 8; ks++) {
            const int kb = ks * 8;
            unsigned pa[2][4];
#pragma unroll
            for (int i = 0; i < 2; i++) {
                const int rb = wr + i * 16;
                pa[i][0] = __float_as_uint(Ps[(rb + r    ) * SLD + kb + c    ]);
                pa[i][1] = __float_as_uint(Ps[(rb + r + 8) * SLD + kb + c    ]);
                pa[i][2] = __float_as_uint(Ps[(rb + r    ) * SLD + kb + c + 4]);
                pa[i][3] = __float_as_uint(Ps[(rb + r + 8) * SLD + kb + c + 4]);
            }
#pragma unroll
            for (int nt = 0; nt < 8; nt++) {
                unsigned b0 = __float_as_uint(Vs[(kb + c    ) * SLD + nt * 8 + r]);
                unsigned b1 = __float_as_uint(Vs[(kb + c + 4) * SLD + nt * 8 + r]);
                mma_tf32(o[0][nt], pa[0][0], pa[0][1], pa[0][2], pa[0][3], b0, b1);
                mma_tf32(o[1][nt], pa[1][0], pa[1][1], pa[1][2], pa[1][3], b0, b1);
            }
        }
        __syncthreads();   // all warps done with stage st before overwrite

        if (t + 2 < NKT) {
            const int kt2 = (t + 2) * 64;
#pragma unroll
            for (int j = 0; j < 8; j++) {
                const int row = l_r0 + j * 8;
                cp_async16(&KsB[st * KV_STAGE + row * SLD + l_c4],
                           &Kg[(size_t)(kt2 + row) * HDIM + l_c4]);
                cp_async16(&VsB[st * KV_STAGE + row * SLD + l_c4],
                           &Vg[(size_t)(kt2 + row) * HDIM + l_c4]);
            }
        }
        CP_COMMIT();
    }

    // epilogue: normalize + tf32-round (AO feeds proj GEMM as mma operand)
    const int b = bh >> 4;
    const int h = bh & 15;
#pragma unroll
    for (int i = 0; i < 2; i++) {
        const float il = 1.0f / lst[i][0];
        const float ih = 1.0f / lst[i][1];
        const int rlo = q0 + wr + i * 16 + r;
        const int rhi = rlo + 8;
        float* dlo = &g_AO[((size_t)(b * SEQ + rlo)) * DIM + h * HDIM];
        float* dhi = &g_AO[((size_t)(b * SEQ + rhi)) * DIM + h * HDIM];
#pragma unroll
        for (int nt = 0; nt < 8; nt++) {
            const int d0 = nt * 8 + c * 2;
            *(float2*)&dlo[d0] = make_float2(tf32r(o[i][nt][0] * il), tf32r(o[i][nt][1] * il));
            *(float2*)&dhi[d0] = make_float2(tf32r(o[i][nt][2] * ih), tf32r(o[i][nt][3] * ih));
        }
    }
}

// ---------------- launch ----------------
extern "C" void kernel_launch(void* const* d_in, const int* in_sizes, int n_in,
                              void* d_out, int out_size)
{
    const float* x  = (const float*)d_in[0];
    const float* y  = (const float*)d_in[1];
    const float* Wq = (const float*)d_in[2];
    const float* Wk = (const float*)d_in[3];
    const float* Wv = (const float*)d_in[4];
    const float* Wp = (const float*)d_in[5];
    const float* bp = (const float*)d_in[6];
    float* out = (float*)d_out;

    float *qb, *kb, *vb, *ao, *xr, *yr, *wr;
    cudaGetSymbolAddress((void**)&qb, g_Q);
    cudaGetSymbolAddress((void**)&kb, g_K);
    cudaGetSymbolAddress((void**)&vb, g_V);
    cudaGetSymbolAddress((void**)&ao, g_AO);
    cudaGetSymbolAddress((void**)&xr, g_Xr);
    cudaGetSymbolAddress((void**)&yr, g_Yr);
    cudaGetSymbolAddress((void**)&wr, g_Wr);

    cudaFuncSetAttribute(gemm_tc<1>, cudaFuncAttributeMaxDynamicSharedMemorySize, GEMM_SMEM);
    cudaFuncSetAttribute(gemm_tc<0>, cudaFuncAttributeMaxDynamicSharedMemorySize, GEMM_SMEM);
    cudaFuncSetAttribute(attn_tc,    cudaFuncAttributeMaxDynamicSharedMemorySize, ATTN_SMEM);

    // prep: round x, y, W once (values identical to per-use cvt.rna)
    prep_xy<<<dim3(ROWS * DIM / 1024, 2), 256>>>(x, y, xr, yr);
    WPtrs wp; wp.W[0] = Wq; wp.W[1] = Wk; wp.W[2] = Wv; wp.W[3] = Wp;
    prep_w<<<dim3(DIM * DIM / 1024, 4), 256>>>(wp, wr);

    // QKV projections: one z-batched launch (z=0: x@Wq, z=1: y@Wk, z=2: y@Wv)
    GemmPtrs qkv;
    qkv.A[0] = xr;  qkv.A[1] = yr;  qkv.A[2] = yr;
    qkv.B[0] = wr;
    qkv.B[1] = wr + (size_t)DIM * DIM;
    qkv.B[2] = wr + 2 * (size_t)DIM * DIM;
    qkv.C[0] = qb;  qkv.C[1] = kb;  qkv.C[2] = vb;
    dim3 qkv_grid(DIM / 128, ROWS / 128, 3);   // (8, 32, 3) = 768 CTAs
    gemm_tc<1><<<qkv_grid, 128, GEMM_SMEM>>>(qkv, nullptr);

    dim3 agrid(SEQ / 128, BATCH * HEADS);      // (16, 32) = 512 CTAs
    attn_tc<<<agrid, 128, ATTN_SMEM>>>(qb, kb, vb, ao);

    // output projection
    GemmPtrs po;
    po.A[0] = ao; po.B[0] = wr + 3 * (size_t)DIM * DIM; po.C[0] = out;
    po.A[1] = po.A[2] = nullptr; po.B[1] = po.B[2] = nullptr; po.C[1] = po.C[2] = nullptr;
    dim3 ogrid(DIM / 128, ROWS / 128, 1);
    gemm_tc<0><<<ogrid, 128, GEMM_SMEM>>>(po, bp);
}